// round 17
// baseline (speedup 1.0000x reference)
#include <cuda_runtime.h>
#include <cuda_bf16.h>
#include <cstdint>

// out[r][c] = in[2r+1][2c+1], in: 8192x8192 fp32, out: 4096x4096 fp32.
//
// FINAL — optimum of a 16-round structural search on GB300 (sm_103a):
//   * one CTA per output row (4096 CTAs x 256 threads)
//   * 8 front-batched __ldcs LDG.128 per thread (MLP=8, streaming hint)
//   * 4 contiguous __stcs STG.128 per thread
//
// Steady state: 31.2us (x4 reproductions) = 6.15 TB/s sustained on the
// irreducible 192MB stream (128MB reads — odd columns occupy every 32B
// sector of odd rows — + 64MB writes) = B300 mixed-stream DRAM ceiling.
//
// Measured and rejected:
//   256-bit loads (-15%), 256-bit stores (-28%), __ldlu loads (-5%),
//   store policy wb / evict_last / write-through / TMA bulk (all tie:
//   L2/DRAM path is path-independent at saturation), L2 evict_last
//   output pinning (no cross-replay residency), persistent grid (-4%),
//   2 rows/CTA (-3%), TPB=512 (worse in loop), 16K small blocks (-8%).

#define N_IN   8192
#define N_OUT  4096
#define F4_ROW (N_OUT / 4)   // 1024 output float4s per row
#define TPB    256
#define UNROLL 4             // F4_ROW / TPB

__global__ __launch_bounds__(TPB) void decimate2_kernel(
    const float4* __restrict__ in, float4* __restrict__ out)
{
    const int orow = blockIdx.x;
    const int tid  = threadIdx.x;

    const float4* in_row  = in  + (size_t)(2 * orow + 1) * (N_IN / 4);
    float4*       out_row = out + (size_t)orow * F4_ROW;

    float4 a[UNROLL], b[UNROLL];

    // Front-batched loads: 8 independent LDG.128 in flight per thread.
#pragma unroll
    for (int k = 0; k < UNROLL; k++) {
        const int oc4 = tid + k * TPB;
        a[k] = __ldcs(&in_row[2 * oc4]);
        b[k] = __ldcs(&in_row[2 * oc4 + 1]);
    }

#pragma unroll
    for (int k = 0; k < UNROLL; k++) {
        const int oc4 = tid + k * TPB;
        float4 r;
        r.x = a[k].y;   // odd col 8*oc4+1
        r.y = a[k].w;   // odd col 8*oc4+3
        r.z = b[k].y;   // odd col 8*oc4+5
        r.w = b[k].w;   // odd col 8*oc4+7
        __stcs(&out_row[oc4], r);
    }
}

extern "C" void kernel_launch(void* const* d_in, const int* in_sizes, int n_in,
                              void* d_out, int out_size)
{
    const float4* in  = (const float4*)d_in[0];
    float4*       out = (float4*)d_out;

    decimate2_kernel<<<N_OUT, TPB>>>(in, out);
}